// round 1
// baseline (speedup 1.0000x reference)
#include <cuda_runtime.h>
#include <cstdint>

// BinCat: out[row] = cats[idx(row)] where
//   idx = sum_j (1 - x[row][j]) << (19 - j),  row in [0, 65536)
//
// One warp per row:
//   lanes 0..19  : load bit j, ballot(x_j == 0) -> mask bit j
//   idx = brev(mask) >> 12   (bit j -> bit 19-j)
//   lanes 0..15  : float4 copy of the 256B embedding row

#define LENGTH 20
#define DIM    64
#define ROWS   (4096 * 16)   // BATCH * I
#define WARPS_PER_BLOCK 8
#define THREADS (WARPS_PER_BLOCK * 32)

__global__ __launch_bounds__(THREADS)
void bincat_kernel(const int* __restrict__ x,
                   const float* __restrict__ cats,
                   float* __restrict__ out)
{
    const int warp_in_block = threadIdx.x >> 5;
    const int lane = threadIdx.x & 31;
    const int row  = blockIdx.x * WARPS_PER_BLOCK + warp_in_block;
    if (row >= ROWS) return;

    // Load this row's 20 bits (lanes 0..19), coalesced 80B per warp.
    int bit = 0;
    if (lane < LENGTH) {
        bit = __ldg(x + (size_t)row * LENGTH + lane);
    }

    // mask bit j set iff x_j == 0 (i.e. (1 - x_j) == 1)
    unsigned mask = __ballot_sync(0xFFFFFFFFu, (lane < LENGTH) && (bit == 0));
    // weight of bit j is 2^(19-j): reverse 32-bit then shift down by 12
    unsigned idx = __brev(mask) >> (32 - LENGTH);

    // Copy 64 floats = 16 x float4, lanes 0..15.
    const float4* __restrict__ src =
        reinterpret_cast<const float4*>(cats + (size_t)idx * DIM);
    float4* __restrict__ dst =
        reinterpret_cast<float4*>(out + (size_t)row * DIM);
    if (lane < (DIM / 4)) {
        dst[lane] = __ldg(src + lane);
    }
}

extern "C" void kernel_launch(void* const* d_in, const int* in_sizes, int n_in,
                              void* d_out, int out_size)
{
    const int*   x    = (const int*)d_in[0];    // (4096, 16, 20) int32
    const float* cats = (const float*)d_in[1];  // (2^20, 64) float32
    float*       out  = (float*)d_out;          // (4096, 16, 64) float32

    const int blocks = ROWS / WARPS_PER_BLOCK;  // 8192
    bincat_kernel<<<blocks, THREADS>>>(x, cats, out);
}

// round 3
// speedup vs baseline: 1.2620x; 1.2620x over previous
#include <cuda_runtime.h>
#include <cstdint>

// BinCat: out[row] = cats[idx(row)],  idx = sum_j (1 - x[row][j]) << (19-j)
//
// Two-phase, high-MLP design:
//  Phase 1: one thread per row. 5 independent int4 loads fetch the 20 bits
//           (MLP=5; x row stride is 80B = 16B-aligned). Bits are disjoint
//           powers of two, so idx = (~m) & 0xFFFFF with
//           m = sum_j x_j << (19-j). Index -> smem.
//  Phase 2: 16 threads per row, 8 rows per iteration, 16 iterations fully
//           unrolled with no loop-carried deps -> ptxas front-batches the
//           independent LDS + LDG.128 gather pairs (MLP ~8-16/thread).
//           Stores are fully coalesced 256B rows.

#define LENGTH 20
#define DIM    64
#define VEC    (DIM / 4)          // 16 float4 per row
#define ROWS   (4096 * 16)        // 65536
#define ROWS_PER_BLOCK 128
#define THREADS 128
#define NBLOCKS (ROWS / ROWS_PER_BLOCK)   // 512

__global__ __launch_bounds__(THREADS)
void bincat_kernel(const int* __restrict__ x,
                   const float* __restrict__ cats,
                   float* __restrict__ out)
{
    __shared__ unsigned s_idx[ROWS_PER_BLOCK];

    const int t    = threadIdx.x;
    const int row0 = blockIdx.x * ROWS_PER_BLOCK;

    // ---- Phase 1: one index per thread ----
    {
        const int4* __restrict__ p =
            reinterpret_cast<const int4*>(x + (size_t)(row0 + t) * LENGTH);
        const int4 a = __ldg(p + 0);
        const int4 b = __ldg(p + 1);
        const int4 c = __ldg(p + 2);
        const int4 d = __ldg(p + 3);
        const int4 e = __ldg(p + 4);

        unsigned m;
        m  = (unsigned)a.x << 19;  m |= (unsigned)a.y << 18;
        m |= (unsigned)a.z << 17;  m |= (unsigned)a.w << 16;
        m |= (unsigned)b.x << 15;  m |= (unsigned)b.y << 14;
        m |= (unsigned)b.z << 13;  m |= (unsigned)b.w << 12;
        m |= (unsigned)c.x << 11;  m |= (unsigned)c.y << 10;
        m |= (unsigned)c.z <<  9;  m |= (unsigned)c.w <<  8;
        m |= (unsigned)d.x <<  7;  m |= (unsigned)d.y <<  6;
        m |= (unsigned)d.z <<  5;  m |= (unsigned)d.w <<  4;
        m |= (unsigned)e.x <<  3;  m |= (unsigned)e.y <<  2;
        m |= (unsigned)e.z <<  1;  m |= (unsigned)e.w;

        s_idx[t] = (~m) & 0xFFFFFu;
    }
    __syncthreads();

    // ---- Phase 2: gather copy, 16 threads/row, 8 rows/iter, unrolled ----
    const int g      = t >> 4;   // 0..7  : which row of the 8 in this iter
    const int lane16 = t & 15;   // 0..15 : float4 slot within the row

    const float4* __restrict__ catsv = reinterpret_cast<const float4*>(cats);
    float4* __restrict__ outv =
        reinterpret_cast<float4*>(out) + (size_t)row0 * VEC;

    #pragma unroll
    for (int k = 0; k < ROWS_PER_BLOCK / 8; k++) {
        const int row_local = k * 8 + g;
        const unsigned idx  = s_idx[row_local];
        const float4 v = __ldg(catsv + (size_t)idx * VEC + lane16);
        outv[(size_t)row_local * VEC + lane16] = v;
    }
}

extern "C" void kernel_launch(void* const* d_in, const int* in_sizes, int n_in,
                              void* d_out, int out_size)
{
    const int*   x    = (const int*)d_in[0];    // (4096, 16, 20) int32
    const float* cats = (const float*)d_in[1];  // (2^20, 64) float32
    float*       out  = (float*)d_out;          // (4096, 16, 64) float32

    bincat_kernel<<<NBLOCKS, THREADS>>>(x, cats, out);
}